// round 4
// baseline (speedup 1.0000x reference)
#include <cuda_runtime.h>
#include <cuda_fp16.h>
#include <math.h>

#define NCH 256

// fp16 transposed [H,W,C] scratch for levels 3..5 (10.5 MB, L2-resident).
// Level 2 (~1.4% of boxes) is gathered directly from raw [C,H,W] fp32 p2.
__device__ __half g_t3[128 * 128 * NCH];  //  8 MB
__device__ __half g_t4[64 * 64 * NCH];    //  2 MB
__device__ __half g_t5[32 * 32 * NCH];    // 0.5 MB

#define NB3T 2048
#define NB4T 512
#define NB5T 128
#define NBT  (NB3T + NB4T + NB5T)

__global__ __launch_bounds__(256) void transpose345(
    const float* __restrict__ p3, const float* __restrict__ p4,
    const float* __restrict__ p5)
{
    __shared__ float tile[64][33];

    int bid = blockIdx.x;
    const float* __restrict__ in;
    __half* __restrict__ out;
    int HW;
    if (bid < NB3T)              { in = p3; out = g_t3; HW = 16384; }
    else if (bid < NB3T + NB4T)  { bid -= NB3T;        in = p4; out = g_t4; HW = 4096; }
    else                         { bid -= NB3T + NB4T; in = p5; out = g_t5; HW = 1024; }

    const int nhw = HW >> 5;
    const int hw0 = (bid % nhw) * 32;
    const int c0  = (bid / nhw) * 64;
    const int tx = threadIdx.x, ty = threadIdx.y;

#pragma unroll
    for (int cc = ty; cc < 64; cc += 8)
        tile[cc][tx] = in[(size_t)(c0 + cc) * HW + hw0 + tx];
    __syncthreads();
#pragma unroll
    for (int hh = ty; hh < 32; hh += 8) {
        __half2 v = __floats2half2_rn(tile[2 * tx][hh], tile[2 * tx + 1][hh]);
        *reinterpret_cast<__half2*>(&out[(size_t)(hw0 + hh) * NCH + c0 + 2 * tx]) = v;
    }
}

// One block (128 threads) per box. Thread t owns channel pair (2t, 2t+1).
// All sample loops are compile-time constant-bound and fully unrolled so
// ptxas can batch ~200 independent loads (the kernel is latency-bound).
__global__ __launch_bounds__(128) void roi_gather(
    const float* __restrict__ boxes, const float* __restrict__ p2,
    float* __restrict__ out)
{
    __shared__ float sm[NCH * 49];  // 50176 B

    const int b = blockIdx.x;
    const float y1 = boxes[4 * b + 0];
    const float x1 = boxes[4 * b + 1];
    const float y2 = boxes[4 * b + 2];
    const float x2 = boxes[4 * b + 3];
    const float h = y2 - y1;
    const float w = x2 - x1;

    const float lvl = 4.0f + log2f(sqrtf(h * w) / 0.21875f);
    int level = (int)rintf(lvl);
    level = min(5, max(2, level));

    const __half* __restrict__ fm16 = g_t5;
    int H = 32;
    if      (level == 2) { H = 256; }
    else if (level == 3) { fm16 = g_t3; H = 128; }
    else if (level == 4) { fm16 = g_t4; H = 64;  }
    const int W = H;
    const float Hm1 = (float)(H - 1);

    int   iy0[7], iy1v[7], ix0[7], ix1[7];
    float lyv[7], lxv[7], vy[7], vx[7];
#pragma unroll
    for (int i = 0; i < 7; i++) {
        const float g  = (float)i / 6.0f;
        const float ys = (y1 + g * h) * Hm1;
        const float xs = (x1 + g * w) * Hm1;
        const float y0f = floorf(ys);
        const float x0f = floorf(xs);
        lyv[i] = ys - y0f;
        lxv[i] = xs - x0f;
        int y0 = min(H - 1, max(0, (int)y0f));
        int x0 = min(W - 1, max(0, (int)x0f));
        iy0[i] = y0; iy1v[i] = min(H - 1, y0 + 1);
        ix0[i] = x0; ix1[i]  = min(W - 1, x0 + 1);
        vy[i] = (ys >= 0.0f && ys <= Hm1) ? 1.0f : 0.0f;
        vx[i] = (xs >= 0.0f && xs <= Hm1) ? 1.0f : 0.0f;
    }

    const int t = threadIdx.x;          // 0..127, channel pair (2t, 2t+1)

    if (level != 2) {
        const __half* __restrict__ base = fm16 + 2 * t;
#pragma unroll
        for (int py = 0; py < 7; py++) {
            const __half* __restrict__ r0 = base + (size_t)iy0[py]  * W * NCH;
            const __half* __restrict__ r1 = base + (size_t)iy1v[py] * W * NCH;
            const float wy1v = lyv[py];
            const float wy0v = 1.0f - wy1v;
            const float vyy = vy[py];
#pragma unroll
            for (int px = 0; px < 7; px++) {
                const float2 f00 = __half22float2(*reinterpret_cast<const __half2*>(r0 + ix0[px] * NCH));
                const float2 f10 = __half22float2(*reinterpret_cast<const __half2*>(r1 + ix0[px] * NCH));
                const float2 f01 = __half22float2(*reinterpret_cast<const __half2*>(r0 + ix1[px] * NCH));
                const float2 f11 = __half22float2(*reinterpret_cast<const __half2*>(r1 + ix1[px] * NCH));
                const float wx1v = lxv[px], wx0v = 1.0f - wx1v;
                const float m = vyy * vx[px];
                const float va = ((f00.x * wy0v + f10.x * wy1v) * wx0v +
                                  (f01.x * wy0v + f11.x * wy1v) * wx1v) * m;
                const float vb = ((f00.y * wy0v + f10.y * wy1v) * wx0v +
                                  (f01.y * wy0v + f11.y * wy1v) * wx1v) * m;
                sm[(2 * t)     * 49 + py * 7 + px] = va;
                sm[(2 * t + 1) * 49 + py * 7 + px] = vb;
            }
        }
    } else {
        const float* __restrict__ basea = p2 + (size_t)(2 * t)     * 65536;
        const float* __restrict__ baseb = p2 + (size_t)(2 * t + 1) * 65536;
#pragma unroll
        for (int py = 0; py < 7; py++) {
            const int o0 = iy0[py] * 256, o1 = iy1v[py] * 256;
            const float wy1v = lyv[py];
            const float wy0v = 1.0f - wy1v;
            const float vyy = vy[py];
#pragma unroll
            for (int px = 0; px < 7; px++) {
                const float wx1v = lxv[px], wx0v = 1.0f - wx1v;
                const float m = vyy * vx[px];
                const float a00 = basea[o0 + ix0[px]];
                const float a10 = basea[o1 + ix0[px]];
                const float a01 = basea[o0 + ix1[px]];
                const float a11 = basea[o1 + ix1[px]];
                const float b00 = baseb[o0 + ix0[px]];
                const float b10 = baseb[o1 + ix0[px]];
                const float b01 = baseb[o0 + ix1[px]];
                const float b11 = baseb[o1 + ix1[px]];
                sm[(2 * t)     * 49 + py * 7 + px] =
                    ((a00 * wy0v + a10 * wy1v) * wx0v + (a01 * wy0v + a11 * wy1v) * wx1v) * m;
                sm[(2 * t + 1) * 49 + py * 7 + px] =
                    ((b00 * wy0v + b10 * wy1v) * wx0v + (b01 * wy0v + b11 * wy1v) * wx1v) * m;
            }
        }
    }
    __syncthreads();

    // Coalesced vectorized write-out: 12544 floats = 3136 float4.
    const float4* __restrict__ sm4 = reinterpret_cast<const float4*>(sm);
    float4* __restrict__ ob = reinterpret_cast<float4*>(out + (size_t)b * (NCH * 49));
#pragma unroll 4
    for (int i = t; i < 3136; i += 128)
        ob[i] = sm4[i];
}

extern "C" void kernel_launch(void* const* d_in, const int* in_sizes, int n_in,
                              void* d_out, int out_size)
{
    const float* boxes = (const float*)d_in[0];
    const float* p2    = (const float*)d_in[1];
    const float* p3    = (const float*)d_in[2];
    const float* p4    = (const float*)d_in[3];
    const float* p5    = (const float*)d_in[4];
    float* out = (float*)d_out;

    transpose345<<<NBT, dim3(32, 8)>>>(p3, p4, p5);

    const int nboxes = in_sizes[0] / 4;
    roi_gather<<<nboxes, 128>>>(boxes, p2, out);
}

// round 5
// speedup vs baseline: 1.6886x; 1.6886x over previous
#include <cuda_runtime.h>
#include <cuda_fp16.h>
#include <math.h>

#define NCH 256

// fp16 transposed [H,W,C] scratch for levels 3..5 (10.5 MB, L2-resident).
// Level 2 (~1.4% of boxes) is gathered directly from raw [C,H,W] fp32 p2.
__device__ __half g_t3[128 * 128 * NCH];  //  8 MB
__device__ __half g_t4[64 * 64 * NCH];    //  2 MB
__device__ __half g_t5[32 * 32 * NCH];    // 0.5 MB

#define NB3T 2048
#define NB4T 512
#define NB5T 128
#define NBT  (NB3T + NB4T + NB5T)

__global__ __launch_bounds__(256) void transpose345(
    const float* __restrict__ p3, const float* __restrict__ p4,
    const float* __restrict__ p5)
{
    __shared__ float tile[64][33];

    int bid = blockIdx.x;
    const float* __restrict__ in;
    __half* __restrict__ out;
    int HW;
    if (bid < NB3T)              { in = p3; out = g_t3; HW = 16384; }
    else if (bid < NB3T + NB4T)  { bid -= NB3T;        in = p4; out = g_t4; HW = 4096; }
    else                         { bid -= NB3T + NB4T; in = p5; out = g_t5; HW = 1024; }

    const int nhw = HW >> 5;
    const int hw0 = (bid % nhw) * 32;
    const int c0  = (bid / nhw) * 64;
    const int tx = threadIdx.x, ty = threadIdx.y;

#pragma unroll
    for (int cc = ty; cc < 64; cc += 8)
        tile[cc][tx] = in[(size_t)(c0 + cc) * HW + hw0 + tx];
    __syncthreads();
#pragma unroll
    for (int hh = ty; hh < 32; hh += 8) {
        __half2 v = __floats2half2_rn(tile[2 * tx][hh], tile[2 * tx + 1][hh]);
        *reinterpret_cast<__half2*>(&out[(size_t)(hw0 + hh) * NCH + c0 + 2 * tx]) = v;
    }
}

// Gather a compile-time py range [P0,P1) for channel pair (2p, 2p+1) using
// __half2 loads (4B payload per register -> 2x bytes-in-flight vs scalar).
template <int P0, int P1>
__device__ __forceinline__ void gather_h2(
    const __half* __restrict__ base,   // fm16 + 2*p
    int W,
    const int* iy0, const int* iy1, const float* lyv, const float* vy,
    const int* ix0, const int* ix1, const float* lxv, const float* vx,
    float* __restrict__ sm, int p)
{
#pragma unroll
    for (int py = P0; py < P1; py++) {
        const __half* __restrict__ r0 = base + (size_t)iy0[py] * W * NCH;
        const __half* __restrict__ r1 = base + (size_t)iy1[py] * W * NCH;
        const float wy1v = lyv[py];
        const float wy0v = 1.0f - wy1v;
        const float vyy = vy[py];
#pragma unroll
        for (int px = 0; px < 7; px++) {
            const float2 f00 = __half22float2(*reinterpret_cast<const __half2*>(r0 + ix0[px] * NCH));
            const float2 f10 = __half22float2(*reinterpret_cast<const __half2*>(r1 + ix0[px] * NCH));
            const float2 f01 = __half22float2(*reinterpret_cast<const __half2*>(r0 + ix1[px] * NCH));
            const float2 f11 = __half22float2(*reinterpret_cast<const __half2*>(r1 + ix1[px] * NCH));
            const float wx1v = lxv[px], wx0v = 1.0f - wx1v;
            const float m = vyy * vx[px];
            sm[(2 * p)     * 49 + py * 7 + px] =
                ((f00.x * wy0v + f10.x * wy1v) * wx0v +
                 (f01.x * wy0v + f11.x * wy1v) * wx1v) * m;
            sm[(2 * p + 1) * 49 + py * 7 + px] =
                ((f00.y * wy0v + f10.y * wy1v) * wx0v +
                 (f01.y * wy0v + f11.y * wy1v) * wx1v) * m;
        }
    }
}

template <int P0, int P1>
__device__ __forceinline__ void gather_f32(
    const float* __restrict__ p2, int p,
    const int* iy0, const int* iy1, const float* lyv, const float* vy,
    const int* ix0, const int* ix1, const float* lxv, const float* vx,
    float* __restrict__ sm)
{
    const float* __restrict__ basea = p2 + (size_t)(2 * p)     * 65536;
    const float* __restrict__ baseb = p2 + (size_t)(2 * p + 1) * 65536;
#pragma unroll
    for (int py = P0; py < P1; py++) {
        const int o0 = iy0[py] * 256, o1 = iy1[py] * 256;
        const float wy1v = lyv[py];
        const float wy0v = 1.0f - wy1v;
        const float vyy = vy[py];
#pragma unroll
        for (int px = 0; px < 7; px++) {
            const float wx1v = lxv[px], wx0v = 1.0f - wx1v;
            const float m = vyy * vx[px];
            const float a00 = basea[o0 + ix0[px]];
            const float a10 = basea[o1 + ix0[px]];
            const float a01 = basea[o0 + ix1[px]];
            const float a11 = basea[o1 + ix1[px]];
            const float b00 = baseb[o0 + ix0[px]];
            const float b10 = baseb[o1 + ix0[px]];
            const float b01 = baseb[o0 + ix1[px]];
            const float b11 = baseb[o1 + ix1[px]];
            sm[(2 * p)     * 49 + py * 7 + px] =
                ((a00 * wy0v + a10 * wy1v) * wx0v + (a01 * wy0v + a11 * wy1v) * wx1v) * m;
            sm[(2 * p + 1) * 49 + py * 7 + px] =
                ((b00 * wy0v + b10 * wy1v) * wx0v + (b01 * wy0v + b11 * wy1v) * wx1v) * m;
        }
    }
}

// One block (256 threads) per box. Thread = (channel pair p = t&127,
// sample-half sh = t>>7). sh==0 -> py 0..3, sh==1 -> py 4..6: both branches
// have compile-time bounds and are fully unrolled. __half2 gather loads.
__global__ __launch_bounds__(256, 3) void roi_gather(
    const float* __restrict__ boxes, const float* __restrict__ p2,
    float* __restrict__ out)
{
    __shared__ float sm[NCH * 49];  // 50176 B

    const int b = blockIdx.x;
    const float y1 = boxes[4 * b + 0];
    const float x1 = boxes[4 * b + 1];
    const float y2 = boxes[4 * b + 2];
    const float x2 = boxes[4 * b + 3];
    const float h = y2 - y1;
    const float w = x2 - x1;

    const float lvl = 4.0f + log2f(sqrtf(h * w) / 0.21875f);
    int level = (int)rintf(lvl);
    level = min(5, max(2, level));

    const __half* __restrict__ fm16 = g_t5;
    int H = 32;
    if      (level == 2) { H = 256; }
    else if (level == 3) { fm16 = g_t3; H = 128; }
    else if (level == 4) { fm16 = g_t4; H = 64;  }
    const int W = H;
    const float Hm1 = (float)(H - 1);

    int   iy0[7], iy1[7], ix0[7], ix1[7];
    float lyv[7], lxv[7], vy[7], vx[7];
#pragma unroll
    for (int i = 0; i < 7; i++) {
        const float g  = (float)i / 6.0f;
        const float ys = (y1 + g * h) * Hm1;
        const float xs = (x1 + g * w) * Hm1;
        const float y0f = floorf(ys);
        const float x0f = floorf(xs);
        lyv[i] = ys - y0f;
        lxv[i] = xs - x0f;
        int y0 = min(H - 1, max(0, (int)y0f));
        int x0 = min(W - 1, max(0, (int)x0f));
        iy0[i] = y0; iy1[i] = min(H - 1, y0 + 1);
        ix0[i] = x0; ix1[i] = min(W - 1, x0 + 1);
        vy[i] = (ys >= 0.0f && ys <= Hm1) ? 1.0f : 0.0f;
        vx[i] = (xs >= 0.0f && xs <= Hm1) ? 1.0f : 0.0f;
    }

    const int t  = threadIdx.x;
    const int p  = t & 127;     // channel pair: channels (2p, 2p+1)
    const int sh = t >> 7;      // sample half

    if (level != 2) {
        const __half* __restrict__ base = fm16 + 2 * p;
        if (sh == 0)
            gather_h2<0, 4>(base, W, iy0, iy1, lyv, vy, ix0, ix1, lxv, vx, sm, p);
        else
            gather_h2<4, 7>(base, W, iy0, iy1, lyv, vy, ix0, ix1, lxv, vx, sm, p);
    } else {
        if (sh == 0)
            gather_f32<0, 4>(p2, p, iy0, iy1, lyv, vy, ix0, ix1, lxv, vx, sm);
        else
            gather_f32<4, 7>(p2, p, iy0, iy1, lyv, vy, ix0, ix1, lxv, vx, sm);
    }
    __syncthreads();

    // Coalesced vectorized write-out: 12544 floats = 3136 float4.
    const float4* __restrict__ sm4 = reinterpret_cast<const float4*>(sm);
    float4* __restrict__ ob = reinterpret_cast<float4*>(out + (size_t)b * (NCH * 49));
#pragma unroll 4
    for (int i = t; i < 3136; i += 256)
        ob[i] = sm4[i];
}

extern "C" void kernel_launch(void* const* d_in, const int* in_sizes, int n_in,
                              void* d_out, int out_size)
{
    const float* boxes = (const float*)d_in[0];
    const float* p2    = (const float*)d_in[1];
    const float* p3    = (const float*)d_in[2];
    const float* p4    = (const float*)d_in[3];
    const float* p5    = (const float*)d_in[4];
    float* out = (float*)d_out;

    transpose345<<<NBT, dim3(32, 8)>>>(p3, p4, p5);

    const int nboxes = in_sizes[0] / 4;
    roi_gather<<<nboxes, 256>>>(boxes, p2, out);
}

// round 6
// speedup vs baseline: 2.5657x; 1.5195x over previous
#include <cuda_runtime.h>
#include <cuda_fp16.h>
#include <math.h>

#define NCH 256

// fp16 transposed [H,W,C] scratch for levels 3..5 (10.5 MB, L2-resident).
// Level 2 (~1.4% of boxes) is gathered directly from raw [C,H,W] fp32 p2.
__device__ __half g_t3[128 * 128 * NCH];  //  8 MB
__device__ __half g_t4[64 * 64 * NCH];    //  2 MB
__device__ __half g_t5[32 * 32 * NCH];    // 0.5 MB

#define NB3T 2048
#define NB4T 512
#define NB5T 128
#define NBT  (NB3T + NB4T + NB5T)

__global__ __launch_bounds__(256) void transpose345(
    const float* __restrict__ p3, const float* __restrict__ p4,
    const float* __restrict__ p5)
{
    __shared__ float tile[64][33];

    int bid = blockIdx.x;
    const float* __restrict__ in;
    __half* __restrict__ out;
    int HW;
    if (bid < NB3T)              { in = p3; out = g_t3; HW = 16384; }
    else if (bid < NB3T + NB4T)  { bid -= NB3T;        in = p4; out = g_t4; HW = 4096; }
    else                         { bid -= NB3T + NB4T; in = p5; out = g_t5; HW = 1024; }

    const int nhw = HW >> 5;
    const int hw0 = (bid % nhw) * 32;
    const int c0  = (bid / nhw) * 64;
    const int tx = threadIdx.x, ty = threadIdx.y;

#pragma unroll
    for (int cc = ty; cc < 64; cc += 8)
        tile[cc][tx] = in[(size_t)(c0 + cc) * HW + hw0 + tx];
    __syncthreads();
#pragma unroll
    for (int hh = ty; hh < 32; hh += 8) {
        __half2 v = __floats2half2_rn(tile[2 * tx][hh], tile[2 * tx + 1][hh]);
        *reinterpret_cast<__half2*>(&out[(size_t)(hw0 + hh) * NCH + c0 + 2 * tx]) = v;
    }
}

// 8 blocks per box: blockIdx = box*8 + chunk. Chunk = 32 channels, all 49
// samples. 256 threads = 16 channel-pairs (p = t&15) x 16 sample-groups
// (sg = t>>4); thread handles samples sg, sg+16, sg+32, sg+48(<49).
// This 8-way split caps the level-2 (scattered [C,H,W]) block at ~4us of
// L1tex wavefront serialization instead of ~30us, killing the straggler tail.
__global__ __launch_bounds__(256) void roi_gather(
    const float* __restrict__ boxes, const float* __restrict__ p2,
    float* __restrict__ out)
{
    __shared__ float sm[32 * 49];   // 6272 B

    const int b = blockIdx.x >> 3;
    const int q = blockIdx.x & 7;   // channel chunk: channels [32q, 32q+32)

    const float y1 = boxes[4 * b + 0];
    const float x1 = boxes[4 * b + 1];
    const float y2 = boxes[4 * b + 2];
    const float x2 = boxes[4 * b + 3];
    const float h = y2 - y1;
    const float w = x2 - x1;

    const float lvl = 4.0f + log2f(sqrtf(h * w) / 0.21875f);
    int level = (int)rintf(lvl);
    level = min(5, max(2, level));

    const __half* __restrict__ fm16 = g_t5;
    int H = 32;
    if      (level == 2) { H = 256; }
    else if (level == 3) { fm16 = g_t3; H = 128; }
    else if (level == 4) { fm16 = g_t4; H = 64;  }
    const int W = H;
    const float Hm1 = (float)(H - 1);

    const int t  = threadIdx.x;
    const int p  = t & 15;          // channel pair within chunk
    const int sg = t >> 4;          // sample group
    const int c  = 32 * q + 2 * p;  // global channel (even of the pair)

    if (level != 2) {
        const __half* __restrict__ base = fm16 + c;
#pragma unroll
        for (int i = 0; i < 4; i++) {
            const int s = sg + 16 * i;
            if (s < 49) {
                const int py = s / 7;
                const int px = s - 7 * py;
                const float gy = (float)py * (1.0f / 6.0f);
                const float gx = (float)px * (1.0f / 6.0f);
                const float ys = (y1 + gy * h) * Hm1;
                const float xs = (x1 + gx * w) * Hm1;
                const float y0f = floorf(ys);
                const float x0f = floorf(xs);
                const float ly = ys - y0f;
                const float lx = xs - x0f;
                const int y0 = min(H - 1, max(0, (int)y0f));
                const int x0 = min(W - 1, max(0, (int)x0f));
                const int y1i = min(H - 1, y0 + 1);
                const int x1i = min(W - 1, x0 + 1);
                const float vv = ((ys >= 0.0f && ys <= Hm1) ? 1.0f : 0.0f) *
                                 ((xs >= 0.0f && xs <= Hm1) ? 1.0f : 0.0f);

                const __half2* r00 = reinterpret_cast<const __half2*>(base + ((size_t)y0  * W + x0 ) * NCH);
                const __half2* r10 = reinterpret_cast<const __half2*>(base + ((size_t)y1i * W + x0 ) * NCH);
                const __half2* r01 = reinterpret_cast<const __half2*>(base + ((size_t)y0  * W + x1i) * NCH);
                const __half2* r11 = reinterpret_cast<const __half2*>(base + ((size_t)y1i * W + x1i) * NCH);
                const float2 f00 = __half22float2(*r00);
                const float2 f10 = __half22float2(*r10);
                const float2 f01 = __half22float2(*r01);
                const float2 f11 = __half22float2(*r11);

                const float wy0v = 1.0f - ly, wy1v = ly;
                const float wx0v = 1.0f - lx, wx1v = lx;
                sm[(2 * p)     * 49 + s] =
                    ((f00.x * wy0v + f10.x * wy1v) * wx0v +
                     (f01.x * wy0v + f11.x * wy1v) * wx1v) * vv;
                sm[(2 * p + 1) * 49 + s] =
                    ((f00.y * wy0v + f10.y * wy1v) * wx0v +
                     (f01.y * wy0v + f11.y * wy1v) * wx1v) * vv;
            }
        }
    } else {
        const float* __restrict__ basea = p2 + (size_t)c * 65536;
        const float* __restrict__ baseb = basea + 65536;
#pragma unroll
        for (int i = 0; i < 4; i++) {
            const int s = sg + 16 * i;
            if (s < 49) {
                const int py = s / 7;
                const int px = s - 7 * py;
                const float gy = (float)py * (1.0f / 6.0f);
                const float gx = (float)px * (1.0f / 6.0f);
                const float ys = (y1 + gy * h) * Hm1;
                const float xs = (x1 + gx * w) * Hm1;
                const float y0f = floorf(ys);
                const float x0f = floorf(xs);
                const float ly = ys - y0f;
                const float lx = xs - x0f;
                const int y0 = min(H - 1, max(0, (int)y0f));
                const int x0 = min(W - 1, max(0, (int)x0f));
                const int y1i = min(H - 1, y0 + 1);
                const int x1i = min(W - 1, x0 + 1);
                const float vv = ((ys >= 0.0f && ys <= Hm1) ? 1.0f : 0.0f) *
                                 ((xs >= 0.0f && xs <= Hm1) ? 1.0f : 0.0f);

                const int o0 = y0 * 256, o1 = y1i * 256;
                const float a00 = basea[o0 + x0];
                const float a10 = basea[o1 + x0];
                const float a01 = basea[o0 + x1i];
                const float a11 = basea[o1 + x1i];
                const float b00 = baseb[o0 + x0];
                const float b10 = baseb[o1 + x0];
                const float b01 = baseb[o0 + x1i];
                const float b11 = baseb[o1 + x1i];

                const float wy0v = 1.0f - ly, wy1v = ly;
                const float wx0v = 1.0f - lx, wx1v = lx;
                sm[(2 * p)     * 49 + s] =
                    ((a00 * wy0v + a10 * wy1v) * wx0v +
                     (a01 * wy0v + a11 * wy1v) * wx1v) * vv;
                sm[(2 * p + 1) * 49 + s] =
                    ((b00 * wy0v + b10 * wy1v) * wx0v +
                     (b01 * wy0v + b11 * wy1v) * wx1v) * vv;
            }
        }
    }
    __syncthreads();

    // Chunk output is contiguous: out[b][32q..32q+32][49] = 1568 floats.
    const float4* __restrict__ sm4 = reinterpret_cast<const float4*>(sm);
    float4* __restrict__ ob =
        reinterpret_cast<float4*>(out + (size_t)b * (NCH * 49) + (size_t)q * (32 * 49));
#pragma unroll
    for (int i = t; i < 392; i += 256)
        ob[i] = sm4[i];
}

extern "C" void kernel_launch(void* const* d_in, const int* in_sizes, int n_in,
                              void* d_out, int out_size)
{
    const float* boxes = (const float*)d_in[0];
    const float* p2    = (const float*)d_in[1];
    const float* p3    = (const float*)d_in[2];
    const float* p4    = (const float*)d_in[3];
    const float* p5    = (const float*)d_in[4];
    float* out = (float*)d_out;

    transpose345<<<NBT, dim3(32, 8)>>>(p3, p4, p5);

    const int nboxes = in_sizes[0] / 4;
    roi_gather<<<8 * nboxes, 256>>>(boxes, p2, out);
}

// round 7
// speedup vs baseline: 3.0278x; 1.1801x over previous
#include <cuda_runtime.h>
#include <cuda_fp16.h>
#include <math.h>

#define NCH 256

// fp16 transposed [H,W,C] scratch for levels 3..5 (10.5 MB, L2-resident).
// Level 2 (~1.4% of boxes) is gathered directly from raw [C,H,W] fp32 p2.
__device__ __half g_t3[128 * 128 * NCH];  //  8 MB
__device__ __half g_t4[64 * 64 * NCH];    //  2 MB
__device__ __half g_t5[32 * 32 * NCH];    // 0.5 MB

#define NB3T 2048
#define NB4T 512
#define NB5T 128
#define NBT  (NB3T + NB4T + NB5T)

__global__ __launch_bounds__(256) void transpose345(
    const float* __restrict__ p3, const float* __restrict__ p4,
    const float* __restrict__ p5)
{
    __shared__ float tile[64][33];

    int bid = blockIdx.x;
    const float* __restrict__ in;
    __half* __restrict__ out;
    int HW;
    if (bid < NB3T)              { in = p3; out = g_t3; HW = 16384; }
    else if (bid < NB3T + NB4T)  { bid -= NB3T;        in = p4; out = g_t4; HW = 4096; }
    else                         { bid -= NB3T + NB4T; in = p5; out = g_t5; HW = 1024; }

    const int nhw = HW >> 5;
    const int hw0 = (bid % nhw) * 32;
    const int c0  = (bid / nhw) * 64;
    const int tx = threadIdx.x, ty = threadIdx.y;

#pragma unroll
    for (int cc = ty; cc < 64; cc += 8)
        tile[cc][tx] = in[(size_t)(c0 + cc) * HW + hw0 + tx];
    __syncthreads();
#pragma unroll
    for (int hh = ty; hh < 32; hh += 8) {
        __half2 v = __floats2half2_rn(tile[2 * tx][hh], tile[2 * tx + 1][hh]);
        *reinterpret_cast<__half2*>(&out[(size_t)(hw0 + hh) * NCH + c0 + 2 * tx]) = v;
    }
}

// 8 blocks per box: blockIdx = box*8 + chunk (32 channels, all 49 samples).
// Phase 1: threads 0..48 precompute, per sample, the 4 neighbor offsets
// (int4, premultiplied for the addressing mode) and the 4 fused bilinear
// weights (float4 = wy*wx*valid) into smem — geometry is computed ONCE per
// block instead of per thread (the R6 profile was issue-bound, alu=45.7%).
// Phase 2: 8 channel-quads x 32 sample-groups; each thread gathers 4
// channels for its samples with 8B loads (LDG.64 = 4 consecutive halfs).
__global__ __launch_bounds__(256) void roi_gather(
    const float* __restrict__ boxes, const float* __restrict__ p2,
    float* __restrict__ out)
{
    __shared__ float  sm[32 * 49];   // 6272 B staging
    __shared__ int4   offs[49];      // neighbor offsets (00,10,01,11)
    __shared__ float4 wts[49];       // fused weights  (w00,w10,w01,w11)

    const int b = blockIdx.x >> 3;
    const int q = blockIdx.x & 7;    // channel chunk: channels [32q, 32q+32)

    const float y1 = boxes[4 * b + 0];
    const float x1 = boxes[4 * b + 1];
    const float y2 = boxes[4 * b + 2];
    const float x2 = boxes[4 * b + 3];
    const float h = y2 - y1;
    const float w = x2 - x1;

    const float lvl = 4.0f + log2f(sqrtf(h * w) / 0.21875f);
    int level = (int)rintf(lvl);
    level = min(5, max(2, level));

    const __half* __restrict__ fm16 = g_t5;
    int H = 32;
    if      (level == 2) { H = 256; }
    else if (level == 3) { fm16 = g_t3; H = 128; }
    else if (level == 4) { fm16 = g_t4; H = 64;  }
    const int W = H;
    const float Hm1 = (float)(H - 1);
    const int mul = (level == 2) ? 1 : NCH;   // offset units

    const int t = threadIdx.x;

    // ---- Phase 1: per-sample geometry (one thread per sample) ----
    if (t < 49) {
        const int py = t / 7;
        const int px = t - 7 * py;
        const float ys = (y1 + (float)py * (1.0f / 6.0f) * h) * Hm1;
        const float xs = (x1 + (float)px * (1.0f / 6.0f) * w) * Hm1;
        const float y0f = floorf(ys);
        const float x0f = floorf(xs);
        const float ly = ys - y0f;
        const float lx = xs - x0f;
        const int y0  = min(H - 1, max(0, (int)y0f));
        const int x0  = min(W - 1, max(0, (int)x0f));
        const int y1i = min(H - 1, y0 + 1);
        const int x1i = min(W - 1, x0 + 1);
        const float vv = ((ys >= 0.0f && ys <= Hm1) ? 1.0f : 0.0f) *
                         ((xs >= 0.0f && xs <= Hm1) ? 1.0f : 0.0f);
        const float wy0 = 1.0f - ly, wy1 = ly;
        const float wx0 = 1.0f - lx, wx1 = lx;
        offs[t] = make_int4((y0  * W + x0 ) * mul, (y1i * W + x0 ) * mul,
                            (y0  * W + x1i) * mul, (y1i * W + x1i) * mul);
        wts[t]  = make_float4(wy0 * wx0 * vv, wy1 * wx0 * vv,
                              wy0 * wx1 * vv, wy1 * wx1 * vv);
    }
    __syncthreads();

    // ---- Phase 2: gather. quad p = t&7 (channels 4p..4p+3), sg = t>>3. ----
    const int p  = t & 7;
    const int sg = t >> 3;            // 0..31
    const int c  = 32 * q + 4 * p;    // first of 4 channels

    if (level != 2) {
        const __half* __restrict__ base = fm16 + c;
#pragma unroll
        for (int i = 0; i < 2; i++) {
            const int s = sg + 32 * i;
            if (s < 49) {
                const int4   o  = offs[s];
                const float4 wv = wts[s];
                const float2 q00 = *reinterpret_cast<const float2*>(base + o.x);
                const float2 q10 = *reinterpret_cast<const float2*>(base + o.y);
                const float2 q01 = *reinterpret_cast<const float2*>(base + o.z);
                const float2 q11 = *reinterpret_cast<const float2*>(base + o.w);
                const float2 a00 = __half22float2(*reinterpret_cast<const __half2*>(&q00.x));
                const float2 b00 = __half22float2(*reinterpret_cast<const __half2*>(&q00.y));
                const float2 a10 = __half22float2(*reinterpret_cast<const __half2*>(&q10.x));
                const float2 b10 = __half22float2(*reinterpret_cast<const __half2*>(&q10.y));
                const float2 a01 = __half22float2(*reinterpret_cast<const __half2*>(&q01.x));
                const float2 b01 = __half22float2(*reinterpret_cast<const __half2*>(&q01.y));
                const float2 a11 = __half22float2(*reinterpret_cast<const __half2*>(&q11.x));
                const float2 b11 = __half22float2(*reinterpret_cast<const __half2*>(&q11.y));
                sm[(c - 32 * q + 0) * 49 + s] =
                    a00.x * wv.x + a10.x * wv.y + a01.x * wv.z + a11.x * wv.w;
                sm[(c - 32 * q + 1) * 49 + s] =
                    a00.y * wv.x + a10.y * wv.y + a01.y * wv.z + a11.y * wv.w;
                sm[(c - 32 * q + 2) * 49 + s] =
                    b00.x * wv.x + b10.x * wv.y + b01.x * wv.z + b11.x * wv.w;
                sm[(c - 32 * q + 3) * 49 + s] =
                    b00.y * wv.x + b10.y * wv.y + b01.y * wv.z + b11.y * wv.w;
            }
        }
    } else {
        const float* __restrict__ b0 = p2 + (size_t)c * 65536;
#pragma unroll
        for (int i = 0; i < 2; i++) {
            const int s = sg + 32 * i;
            if (s < 49) {
                const int4   o  = offs[s];
                const float4 wv = wts[s];
#pragma unroll
                for (int j = 0; j < 4; j++) {
                    const float* __restrict__ bj = b0 + (size_t)j * 65536;
                    sm[(4 * p + j) * 49 + s] =
                        bj[o.x] * wv.x + bj[o.y] * wv.y +
                        bj[o.z] * wv.z + bj[o.w] * wv.w;
                }
            }
        }
    }
    __syncthreads();

    // Chunk output is contiguous: out[b][32q..32q+32][49] = 1568 floats.
    const float4* __restrict__ sm4 = reinterpret_cast<const float4*>(sm);
    float4* __restrict__ ob =
        reinterpret_cast<float4*>(out + (size_t)b * (NCH * 49) + (size_t)q * (32 * 49));
#pragma unroll
    for (int i = t; i < 392; i += 256)
        ob[i] = sm4[i];
}

extern "C" void kernel_launch(void* const* d_in, const int* in_sizes, int n_in,
                              void* d_out, int out_size)
{
    const float* boxes = (const float*)d_in[0];
    const float* p2    = (const float*)d_in[1];
    const float* p3    = (const float*)d_in[2];
    const float* p4    = (const float*)d_in[3];
    const float* p5    = (const float*)d_in[4];
    float* out = (float*)d_out;

    transpose345<<<NBT, dim3(32, 8)>>>(p3, p4, p5);

    const int nboxes = in_sizes[0] / 4;
    roi_gather<<<8 * nboxes, 256>>>(boxes, p2, out);
}